// round 5
// baseline (speedup 1.0000x reference)
#include <cuda_runtime.h>
#include <cooperative_groups.h>
#include <cstdint>

namespace cg = cooperative_groups;

using u64 = unsigned long long;

// Problem constants
constexpr int B = 32;
constexpr int N = 131072;
constexpr int K = 1024;

// Config
constexpr int C   = 4;             // CTAs per batch (cluster)
constexpr int T   = 1024;          // threads per CTA (32 warps)
constexpr int S   = N / C;         // 32768 points per CTA slice
constexpr int PIN = 16384;         // coords pinned in SMEM
constexpr int STR = S - PIN;       // coords streamed from L2
constexpr int JP  = PIN / (4 * T); // 4 float4-groups per thread (pinned)
constexpr int JQ  = STR / (4 * T); // 4 float4-groups per thread (streamed)

// SoA scratch (static device arrays: allocation-free), 16B aligned for LD.128
__device__ __align__(16) float g_sx[B * N];
__device__ __align__(16) float g_sy[B * N];
__device__ __align__(16) float g_sz[B * N];

__global__ void transpose_kernel(const float* __restrict__ pts) {
    int i = blockIdx.x * blockDim.x + threadIdx.x;
    if (i < B * N) {
        g_sx[i] = pts[3 * i + 0];
        g_sy[i] = pts[3 * i + 1];
        g_sz[i] = pts[3 * i + 2];
    }
}

// ---- Blackwell packed f32x2 helpers (FFMA2 path; ptxas won't auto-fuse) ----
__device__ __forceinline__ u64 pk2(float a, float b) {
    u64 r; asm("mov.b64 %0, {%1, %2};" : "=l"(r) : "f"(a), "f"(b)); return r;
}
__device__ __forceinline__ void upk2(float& a, float& b, u64 v) {
    asm("mov.b64 {%0, %1}, %2;" : "=f"(a), "=f"(b) : "l"(v));
}
__device__ __forceinline__ u64 add2(u64 a, u64 b) {
    u64 r; asm("add.rn.f32x2 %0, %1, %2;" : "=l"(r) : "l"(a), "l"(b)); return r;
}
__device__ __forceinline__ u64 mul2(u64 a, u64 b) {
    u64 r; asm("mul.rn.f32x2 %0, %1, %2;" : "=l"(r) : "l"(a), "l"(b)); return r;
}
__device__ __forceinline__ u64 fma2(u64 a, u64 b, u64 c) {
    u64 r; asm("fma.rn.f32x2 %0, %1, %2, %3;" : "=l"(r) : "l"(a), "l"(b), "l"(c)); return r;
}

// Exchange slot: packed best + winner coords
struct __align__(32) Slot {
    unsigned int lo, hi;   // packed best: (dist_bits << 32) | ~idx
    float x, y, z;
    float pad0, pad1, pad2;
};

// SMEM layout (bytes)
constexpr int SMEM_X  = 0;                       // PIN floats
constexpr int SMEM_Y  = SMEM_X + PIN * 4;
constexpr int SMEM_Z  = SMEM_Y + PIN * 4;
constexpr int SMEM_SL = SMEM_Z + PIN * 4;        // Slot[2][C]
constexpr int SMEM_WB = SMEM_SL + 2 * C * 32;    // u64 wb[32]
constexpr int SMEM_TOTAL = SMEM_WB + 32 * 8;     // ~197 KB

// distance+update for 4 points given packed coord pairs
__device__ __forceinline__ void quad(
    ulonglong2 vx, ulonglong2 vy, ulonglong2 vz,
    u64 nlx, u64 nly, u64 nlz,
    float* d4, float& bd)
{
    u64 dxa = add2(vx.x, nlx), dxb = add2(vx.y, nlx);
    u64 dya = add2(vy.x, nly), dyb = add2(vy.y, nly);
    u64 dza = add2(vz.x, nlz), dzb = add2(vz.y, nlz);
    u64 sa = mul2(dza, dza); sa = fma2(dya, dya, sa); sa = fma2(dxa, dxa, sa);
    u64 sb = mul2(dzb, dzb); sb = fma2(dyb, dyb, sb); sb = fma2(dxb, dxb, sb);
    float d0, d1, d2, d3;
    upk2(d0, d1, sa);
    upk2(d2, d3, sb);
    d4[0] = fminf(d4[0], d0); bd = fmaxf(bd, d4[0]);
    d4[1] = fminf(d4[1], d1); bd = fmaxf(bd, d4[1]);
    d4[2] = fminf(d4[2], d2); bd = fmaxf(bd, d4[2]);
    d4[3] = fminf(d4[3], d3); bd = fmaxf(bd, d4[3]);
}

__global__ void __cluster_dims__(C, 1, 1) __launch_bounds__(T, 1)
fps_kernel(const int* __restrict__ init_idx, float* __restrict__ out)
{
    extern __shared__ char smem[];
    ulonglong2* sx2 = (ulonglong2*)(smem + SMEM_X);
    ulonglong2* sy2 = (ulonglong2*)(smem + SMEM_Y);
    ulonglong2* sz2 = (ulonglong2*)(smem + SMEM_Z);
    Slot* sl = (Slot*)(smem + SMEM_SL);
    u64*  wb = (u64*)(smem + SMEM_WB);

    cg::cluster_group cluster = cg::this_cluster();
    const int rank  = blockIdx.x;
    const int b     = blockIdx.y;
    const int t     = threadIdx.x;
    const int lbase = rank * S;
    const int bOff  = b * N;
    const int gbase = bOff + lbase;
    const int warp  = t >> 5, lane = t & 31;

    const ulonglong2* __restrict__ gx2 = (const ulonglong2*)(g_sx + gbase);
    const ulonglong2* __restrict__ gy2 = (const ulonglong2*)(g_sy + gbase);
    const ulonglong2* __restrict__ gz2 = (const ulonglong2*)(g_sz + gbase);
    const int strBase = PIN / 4;   // streamed region start, float4 units

    // ---- init: pin first PIN points' coords into SMEM ----
    #pragma unroll
    for (int j = 0; j < JP; j++) {
        int fi = t + j * T;
        sx2[fi] = gx2[fi];
        sy2[fi] = gy2[fi];
        sz2[fi] = gz2[fi];
    }

    // all dist in registers: [0,16) pinned, [16,32) streamed
    float dist[32];
    #pragma unroll
    for (int j = 0; j < 32; j++) dist[j] = 1e10f;

    // first selected point (broadcast read)
    const int idx0 = init_idx[b];
    float lx = g_sx[bOff + idx0];
    float ly = g_sy[bOff + idx0];
    float lz = g_sz[bOff + idx0];
    if (rank == 0 && t == 0) {
        out[(b * K + 0) * 3 + 0] = lx;
        out[(b * K + 0) * 3 + 1] = ly;
        out[(b * K + 0) * 3 + 2] = lz;
    }
    __syncthreads();

    // ---- K-1 sequential FPS iterations ----
    for (int k = 1; k < K; k++) {
        // packed negated last-point coords
        u64 nlx = pk2(-lx, -lx);
        u64 nly = pk2(-ly, -ly);
        u64 nlz = pk2(-lz, -lz);

        float bd = -1.0f;   // best (max) updated-dist value this thread

        // streamed points (front-batched LDG.128s)
        #pragma unroll
        for (int j = 0; j < JQ; j++) {
            int fi = strBase + t + j * T;
            quad(gx2[fi], gy2[fi], gz2[fi], nlx, nly, nlz,
                 &dist[16 + j * 4], bd);
        }
        // pinned points (LDS.128)
        #pragma unroll
        for (int j = 0; j < JP; j++) {
            int fi = t + j * T;
            quad(sx2[fi], sy2[fi], sz2[fi], nlx, nly, nlz,
                 &dist[j * 4], bd);
        }

        // warp butterfly max (all lanes get warp max)
        float wv = bd;
        #pragma unroll
        for (int o = 16; o > 0; o >>= 1)
            wv = fmaxf(wv, __shfl_xor_sync(0xffffffffu, wv, o));

        // index recovery: only matching threads rescan their registers
        unsigned mi = 0xffffffffu;
        if (bd == wv) {
            int r = 0;
            #pragma unroll
            for (int j = 31; j >= 0; j--)
                if (dist[j] == bd) r = j;     // lowest matching reg
            int rr = r & 15;
            // reg r -> global (in-batch) index; reg order == index order
            mi = (unsigned)(lbase + ((r & 16) ? PIN : 0) + 4 * t +
                            ((rr >> 2) << 12) + (rr & 3));
        }
        #pragma unroll
        for (int o = 16; o > 0; o >>= 1)
            mi = min(mi, __shfl_xor_sync(0xffffffffu, mi, o));

        if (lane == 0)
            wb[warp] = ((u64)__float_as_uint(wv) << 32) | (u64)(~mi);
        __syncthreads();

        // block reduce (32 warps) + fetch candidate coords + push to ranks
        if (warp == 0) {
            u64 best = wb[lane];
            #pragma unroll
            for (int o = 16; o > 0; o >>= 1) {
                u64 v = __shfl_down_sync(0xffffffffu, best, o);
                if (v > best) best = v;
            }
            if (lane == 0) {
                unsigned cidx = ~(unsigned)(best & 0xffffffffull);
                int loc = (int)cidx - lbase;           // in-slice index
                float cx, cy, cz;
                if (loc < PIN) {
                    cx = ((const float*)sx2)[loc];
                    cy = ((const float*)sy2)[loc];
                    cz = ((const float*)sz2)[loc];
                } else {
                    cx = g_sx[bOff + cidx];
                    cy = g_sy[bOff + cidx];
                    cz = g_sz[bOff + cidx];
                }
                Slot* my = &sl[(k & 1) * C + rank];
                uint4 w = make_uint4((unsigned)(best & 0xffffffffull),
                                     (unsigned)(best >> 32),
                                     __float_as_uint(cx),
                                     __float_as_uint(cy));
                #pragma unroll
                for (int r = 0; r < C; r++) {
                    Slot* p = (Slot*)cluster.map_shared_rank(my, r);
                    *(uint4*)p = w;
                    p->z = cz;
                }
            }
        }

        cluster.sync();   // orders remote slot stores; acquire for local reads

        // every thread picks the cluster winner from local slots
        u64 gb = 0ULL;
        float nx = 0.f, ny = 0.f, nz = 0.f;
        #pragma unroll
        for (int r = 0; r < C; r++) {
            const Slot* p = &sl[(k & 1) * C + r];
            uint4 w = *(const uint4*)p;
            float z = p->z;
            u64 v = ((u64)w.y << 32) | w.x;
            if (v > gb) {
                gb = v;
                nx = __uint_as_float(w.z);
                ny = __uint_as_float(w.w);
                nz = z;
            }
        }
        lx = nx; ly = ny; lz = nz;

        if (rank == 0 && t == 0) {
            out[(b * K + k) * 3 + 0] = lx;
            out[(b * K + k) * 3 + 1] = ly;
            out[(b * K + k) * 3 + 2] = lz;
        }
    }

    cluster.sync();   // keep SMEM alive until peer traffic has retired
}

extern "C" void kernel_launch(void* const* d_in, const int* in_sizes, int n_in,
                              void* d_out, int out_size) {
    const float* pts  = (const float*)d_in[0];
    const int*   init = (const int*)d_in[1];
    float*       out  = (float*)d_out;

    cudaFuncSetAttribute(fps_kernel,
                         cudaFuncAttributeMaxDynamicSharedMemorySize, SMEM_TOTAL);

    int total = B * N;
    transpose_kernel<<<(total + 255) / 256, 256>>>(pts);

    dim3 grid(C, B, 1);
    fps_kernel<<<grid, T, SMEM_TOTAL>>>(init, out);
}

// round 6
// speedup vs baseline: 1.5310x; 1.5310x over previous
#include <cuda_runtime.h>
#include <cooperative_groups.h>
#include <cstdint>

namespace cg = cooperative_groups;
using u64 = unsigned long long;
using u32 = unsigned int;

// Problem constants
constexpr int B = 32;
constexpr int N = 131072;
constexpr int K = 1024;

// Config
constexpr int C     = 4;        // CTAs per batch (cluster)
constexpr int T     = 1024;     // threads per CTA
constexpr int S     = N / C;    // 32768 pts per CTA slice
constexpr int CH    = 256;      // points per chunk
constexpr int NCH   = S / CH;   // 128 chunks per CTA
constexpr int CELLS = 4096;     // 16^3 Morton cells per batch
constexpr int CHB   = N / CH;   // 512 chunks per batch

// Static device scratch (allocation-free)
__device__ __align__(16) float g_sx[B * N];   // sorted SoA coords
__device__ __align__(16) float g_sy[B * N];
__device__ __align__(16) float g_sz[B * N];
__device__ __align__(16) int   g_oi[B * N];   // original within-batch index
__device__ int   g_hist[B * CELLS];
__device__ int   g_cur[B * CELLS];
__device__ float g_bbox[B * CHB * 6];

// ---- Morton cell id (4 bits/dim) ----
__device__ __forceinline__ u32 expand3_4(u32 v) {
    return (v & 1u) | ((v & 2u) << 2) | ((v & 4u) << 4) | ((v & 8u) << 6);
}
__device__ __forceinline__ int cell_of(float x, float y, float z) {
    int ix = min(15, max(0, (int)((x + 4.5f) * (16.0f / 9.0f))));
    int iy = min(15, max(0, (int)((y + 4.5f) * (16.0f / 9.0f))));
    int iz = min(15, max(0, (int)((z + 4.5f) * (16.0f / 9.0f))));
    return (int)(expand3_4((u32)ix) | (expand3_4((u32)iy) << 1) |
                 (expand3_4((u32)iz) << 2));
}

// ---- Preprocessing kernels ----
__global__ void zero_hist_kernel() {
    int i = blockIdx.x * blockDim.x + threadIdx.x;
    if (i < B * CELLS) g_hist[i] = 0;
}

__global__ void cell_hist_kernel(const float* __restrict__ pts) {
    int i = blockIdx.x * blockDim.x + threadIdx.x;
    if (i >= B * N) return;
    float x = pts[3 * i], y = pts[3 * i + 1], z = pts[3 * i + 2];
    int c = cell_of(x, y, z);
    atomicAdd(&g_hist[(i / N) * CELLS + c], 1);
}

// exclusive scan of 4096 cell counts per batch (one CTA per batch)
__global__ void cell_scan_kernel() {
    __shared__ int wt[32];
    int b = blockIdx.x, t = threadIdx.x;
    int lane = t & 31, w = t >> 5;
    int v[4], s = 0;
    #pragma unroll
    for (int j = 0; j < 4; j++) { v[j] = g_hist[b * CELLS + t * 4 + j]; s += v[j]; }
    int ps = s;
    #pragma unroll
    for (int o = 1; o < 32; o <<= 1) {
        int u = __shfl_up_sync(0xffffffffu, ps, o);
        if (lane >= o) ps += u;
    }
    if (lane == 31) wt[w] = ps;
    __syncthreads();
    if (w == 0) {
        int x = wt[lane];
        #pragma unroll
        for (int o = 1; o < 32; o <<= 1) {
            int u = __shfl_up_sync(0xffffffffu, x, o);
            if (lane >= o) x += u;
        }
        wt[lane] = x;
    }
    __syncthreads();
    int run = (w > 0 ? wt[w - 1] : 0) + (ps - s);
    #pragma unroll
    for (int j = 0; j < 4; j++) { g_cur[b * CELLS + t * 4 + j] = run; run += v[j]; }
}

__global__ void scatter_kernel(const float* __restrict__ pts) {
    int i = blockIdx.x * blockDim.x + threadIdx.x;
    if (i >= B * N) return;
    int b = i / N, j = i - b * N;
    float x = pts[3 * i], y = pts[3 * i + 1], z = pts[3 * i + 2];
    int c = cell_of(x, y, z);
    int pos = atomicAdd(&g_cur[b * CELLS + c], 1);
    int o = b * N + pos;
    g_sx[o] = x; g_sy[o] = y; g_sz[o] = z; g_oi[o] = j;
}

// per-chunk bounding box (one 256-thread block per chunk)
__global__ void chunk_bbox_kernel() {
    __shared__ float rmn[3][8], rmx[3][8];
    int ch = blockIdx.x, t = threadIdx.x;
    int lane = t & 31, w = t >> 5;
    int o = ch * CH + t;
    float x = g_sx[o], y = g_sy[o], z = g_sz[o];
    float mnx = x, mxx = x, mny = y, mxy = y, mnz = z, mxz = z;
    #pragma unroll
    for (int s = 16; s > 0; s >>= 1) {
        mnx = fminf(mnx, __shfl_xor_sync(0xffffffffu, mnx, s));
        mxx = fmaxf(mxx, __shfl_xor_sync(0xffffffffu, mxx, s));
        mny = fminf(mny, __shfl_xor_sync(0xffffffffu, mny, s));
        mxy = fmaxf(mxy, __shfl_xor_sync(0xffffffffu, mxy, s));
        mnz = fminf(mnz, __shfl_xor_sync(0xffffffffu, mnz, s));
        mxz = fmaxf(mxz, __shfl_xor_sync(0xffffffffu, mxz, s));
    }
    if (lane == 0) {
        rmn[0][w] = mnx; rmx[0][w] = mxx;
        rmn[1][w] = mny; rmx[1][w] = mxy;
        rmn[2][w] = mnz; rmx[2][w] = mxz;
    }
    __syncthreads();
    if (t == 0) {
        float a0 = rmn[0][0], b0 = rmx[0][0];
        float a1 = rmn[1][0], b1 = rmx[1][0];
        float a2 = rmn[2][0], b2 = rmx[2][0];
        #pragma unroll
        for (int i = 1; i < 8; i++) {
            a0 = fminf(a0, rmn[0][i]); b0 = fmaxf(b0, rmx[0][i]);
            a1 = fminf(a1, rmn[1][i]); b1 = fmaxf(b1, rmx[1][i]);
            a2 = fminf(a2, rmn[2][i]); b2 = fmaxf(b2, rmx[2][i]);
        }
        float* bb = &g_bbox[ch * 6];
        bb[0] = a0; bb[1] = b0; bb[2] = a1; bb[3] = b1; bb[4] = a2; bb[5] = b2;
    }
}

// ---- Main FPS kernel ----
struct __align__(32) Slot {
    u32 lo, hi;        // packed best: (dist_bits<<32) | ~origidx
    float x, y, z;
    float pad0, pad1, pad2;
};

// SMEM layout (bytes)
constexpr int SM_DIST = 0;                       // S floats = 131072
constexpr int SM_BOX  = SM_DIST + S * 4;         // NCH*6 floats = 3072
constexpr int SM_CB   = SM_BOX + NCH * 24;       // NCH u64 = 1024
constexpr int SM_CP   = SM_CB + NCH * 8;         // NCH u32 = 512
constexpr int SM_WL   = SM_CP + NCH * 4;         // NCH u32 = 512
constexpr int SM_WC   = SM_WL + NCH * 4;         // u32 + pad = 32
constexpr int SM_SL   = SM_WC + 32;              // Slot[2][C] = 256
constexpr int SMEM_TOTAL = SM_SL + 2 * C * 32;   // 136,480 B

__global__ void __cluster_dims__(C, 1, 1) __launch_bounds__(T, 1)
fps_kernel(const float* __restrict__ pts, const int* __restrict__ init_idx,
           float* __restrict__ out)
{
    extern __shared__ char smem[];
    float* sdist = (float*)(smem + SM_DIST);
    float* sbox  = (float*)(smem + SM_BOX);
    u64*   scb   = (u64*)(smem + SM_CB);
    u32*   scp   = (u32*)(smem + SM_CP);
    u32*   swl   = (u32*)(smem + SM_WL);
    u32*   swc   = (u32*)(smem + SM_WC);
    Slot*  sl    = (Slot*)(smem + SM_SL);

    cg::cluster_group cluster = cg::this_cluster();
    const int rank  = blockIdx.x;
    const int b     = blockIdx.y;
    const int t     = threadIdx.x;
    const int warp  = t >> 5, lane = t & 31;
    const int gbase = b * N + rank * S;            // slice start, sorted arrays
    const int chbase = b * CHB + rank * NCH;       // slice start, bbox array

    const float4* __restrict__ gx4 = (const float4*)(g_sx + gbase);
    const float4* __restrict__ gy4 = (const float4*)(g_sy + gbase);
    const float4* __restrict__ gz4 = (const float4*)(g_sz + gbase);
    const int4*   __restrict__ go4 = (const int4*)(g_oi + gbase);
    float4* sd4 = (float4*)sdist;

    // ---- init ----
    #pragma unroll
    for (int j = 0; j < S / T; j++) sdist[t + j * T] = 1e10f;
    if (t < NCH) {
        #pragma unroll
        for (int d = 0; d < 6; d++) sbox[t * 6 + d] = g_bbox[(chbase + t) * 6 + d];
        scb[t] = ((u64)__float_as_uint(1e10f)) << 32;  // forces touch at k=1
        scp[t] = 0;
    }

    const int idx0 = init_idx[b];
    float lx = pts[3 * (b * N + idx0) + 0];
    float ly = pts[3 * (b * N + idx0) + 1];
    float lz = pts[3 * (b * N + idx0) + 2];
    if (rank == 0 && t == 0) {
        out[(b * K + 0) * 3 + 0] = lx;
        out[(b * K + 0) * 3 + 1] = ly;
        out[(b * K + 0) * 3 + 2] = lz;
    }
    __syncthreads();

    // ---- K-1 sequential iterations ----
    for (int k = 1; k < K; k++) {
        if (t == 0) *swc = 0;
        __syncthreads();

        // phase 0: bound check, build worklist of touched chunks
        if (t < NCH) {
            const float* bb = &sbox[t * 6];
            float dx = fmaxf(0.0f, fmaxf(bb[0] - lx, lx - bb[1]));
            float dy = fmaxf(0.0f, fmaxf(bb[2] - ly, ly - bb[3]));
            float dz = fmaxf(0.0f, fmaxf(bb[4] - lz, lz - bb[5]));
            float lb2 = __fmaf_rn(dx, dx, __fmaf_rn(dy, dy, dz * dz));
            float cub = __uint_as_float((u32)(scb[t] >> 32));
            if (lb2 * 0.99999f < cub) {   // conservative margin
                u32 p = atomicAdd(swc, 1u);
                swl[p] = (u32)t;
            }
        }
        __syncthreads();
        const int nw = (int)*swc;

        // phase 1: warps update touched chunks (256 pts each)
        for (int wi = warp; wi < nw; wi += 32) {
            int c = (int)swl[wi];
            int f0 = c * 64 + lane;     // float4 index within slice
            int f1 = f0 + 32;
            float4 X0 = gx4[f0], X1 = gx4[f1];
            float4 Y0 = gy4[f0], Y1 = gy4[f1];
            float4 Z0 = gz4[f0], Z1 = gz4[f1];
            int4   O0 = go4[f0], O1 = go4[f1];
            float4 D0 = sd4[f0], D1 = sd4[f1];

            u64 bk = 0ULL; u32 bp = 0;
            {
                const float* X = (const float*)&X0; const float* Y = (const float*)&Y0;
                const float* Z = (const float*)&Z0; float* D = (float*)&D0;
                const int*   O = (const int*)&O0;
                #pragma unroll
                for (int cc = 0; cc < 4; cc++) {
                    float dx = X[cc] - lx, dy = Y[cc] - ly, dz = Z[cc] - lz;
                    float d2 = __fmaf_rn(dx, dx, __fmaf_rn(dy, dy, dz * dz));
                    float nd = fminf(D[cc], d2);
                    D[cc] = nd;
                    u64 key = (((u64)__float_as_uint(nd)) << 32) | (u32)(~(u32)O[cc]);
                    if (key > bk) { bk = key; bp = (u32)(4 * f0 + cc); }
                }
            }
            {
                const float* X = (const float*)&X1; const float* Y = (const float*)&Y1;
                const float* Z = (const float*)&Z1; float* D = (float*)&D1;
                const int*   O = (const int*)&O1;
                #pragma unroll
                for (int cc = 0; cc < 4; cc++) {
                    float dx = X[cc] - lx, dy = Y[cc] - ly, dz = Z[cc] - lz;
                    float d2 = __fmaf_rn(dx, dx, __fmaf_rn(dy, dy, dz * dz));
                    float nd = fminf(D[cc], d2);
                    D[cc] = nd;
                    u64 key = (((u64)__float_as_uint(nd)) << 32) | (u32)(~(u32)O[cc]);
                    if (key > bk) { bk = key; bp = (u32)(4 * f1 + cc); }
                }
            }
            sd4[f0] = D0;
            sd4[f1] = D1;

            // warp reduce (key, pos)
            #pragma unroll
            for (int o = 16; o > 0; o >>= 1) {
                u64 ok = __shfl_xor_sync(0xffffffffu, bk, o);
                u32 op = __shfl_xor_sync(0xffffffffu, bp, o);
                if (ok > bk) { bk = ok; bp = op; }
            }
            if (lane == 0) { scb[c] = bk; scp[c] = bp; }
        }
        __syncthreads();

        // block winner over 128 chunk entries (warp 0), then push to ranks
        if (warp == 0) {
            u64 bk = 0ULL; u32 bp = 0;
            #pragma unroll
            for (int i = 0; i < NCH / 32; i++) {
                u64 e = scb[lane + 32 * i];
                u32 p = scp[lane + 32 * i];
                if (e > bk) { bk = e; bp = p; }
            }
            #pragma unroll
            for (int o = 16; o > 0; o >>= 1) {
                u64 ok = __shfl_xor_sync(0xffffffffu, bk, o);
                u32 op = __shfl_xor_sync(0xffffffffu, bp, o);
                if (ok > bk) { bk = ok; bp = op; }
            }
            if (lane == 0) {
                float cx = g_sx[gbase + (int)bp];
                float cy = g_sy[gbase + (int)bp];
                float cz = g_sz[gbase + (int)bp];
                Slot* my = &sl[(k & 1) * C + rank];
                uint4 w = make_uint4((u32)(bk & 0xffffffffull), (u32)(bk >> 32),
                                     __float_as_uint(cx), __float_as_uint(cy));
                #pragma unroll
                for (int r = 0; r < C; r++) {
                    Slot* p = (Slot*)cluster.map_shared_rank(my, r);
                    *(uint4*)p = w;
                    p->z = cz;
                }
            }
        }

        cluster.sync();   // orders remote slot stores; acquire for local reads

        // every thread picks the cluster winner from local slots
        u64 gb = 0ULL;
        float nx = 0.f, ny = 0.f, nz = 0.f;
        #pragma unroll
        for (int r = 0; r < C; r++) {
            const Slot* p = &sl[(k & 1) * C + r];
            uint4 w = *(const uint4*)p;
            float z = p->z;
            u64 v = ((u64)w.y << 32) | w.x;
            if (v > gb) {
                gb = v;
                nx = __uint_as_float(w.z);
                ny = __uint_as_float(w.w);
                nz = z;
            }
        }
        lx = nx; ly = ny; lz = nz;

        if (rank == 0 && t == 0) {
            out[(b * K + k) * 3 + 0] = lx;
            out[(b * K + k) * 3 + 1] = ly;
            out[(b * K + k) * 3 + 2] = lz;
        }
    }

    cluster.sync();   // keep SMEM alive until peer traffic has retired
}

extern "C" void kernel_launch(void* const* d_in, const int* in_sizes, int n_in,
                              void* d_out, int out_size) {
    const float* pts  = (const float*)d_in[0];
    const int*   init = (const int*)d_in[1];
    float*       out  = (float*)d_out;

    cudaFuncSetAttribute(fps_kernel,
                         cudaFuncAttributeMaxDynamicSharedMemorySize, SMEM_TOTAL);

    const int tot = B * N;
    zero_hist_kernel<<<(B * CELLS + 255) / 256, 256>>>();
    cell_hist_kernel<<<(tot + 255) / 256, 256>>>(pts);
    cell_scan_kernel<<<B, 1024>>>();
    scatter_kernel<<<(tot + 255) / 256, 256>>>(pts);
    chunk_bbox_kernel<<<B * CHB, 256>>>();

    dim3 grid(C, B, 1);
    fps_kernel<<<grid, T, SMEM_TOTAL>>>(pts, init, out);
}